// round 2
// baseline (speedup 1.0000x reference)
#include <cuda_runtime.h>
#include <math.h>

#define TT 10
#define CH 16
#define HH 16
#define WW 264
#define HW (HH*WW)            // 4224
#define DD (CH*HH*WW)         // 67584
#define NPAIR 45              // valid (b,t) warp pairs, t in [1,b]
#define NDOT 55               // (b,i) dot-row tasks, i in [0,b]
#define NCHUNK 8

// Scratch (static device globals; no allocation allowed)
__device__ float g_warp[NPAIR * DD];      // 45 warped rows, compact
__device__ float g_pose[NPAIR * 4];       // cos, sin, dx, dy per pair
__device__ int   g_src[NPAIR];            // source frame t per pair
__device__ float g_dots[TT * 10 * 10];    // per-b row-space Gram (i<=j filled)
__device__ float g_wrow[TT * 10];         // per-b weights in row space

__device__ __forceinline__ int tri(int b) { return b * (b - 1) / 2; } // off[b]

// ---------------------------------------------------------------------------
// Kernel 1: cumsum poses, pair params, zero dot accumulators
// ---------------------------------------------------------------------------
__global__ void pose_kernel(const float* __restrict__ dp) {
    __shared__ float P[TT + 1][3];
    int tid = threadIdx.x;
    if (tid == 0) {
        P[0][0] = P[0][1] = P[0][2] = 0.f;
        for (int k = 1; k <= TT; k++)
            for (int a = 0; a < 3; a++)
                P[k][a] = P[k - 1][a] + dp[(k - 1) * 3 + a];
    }
    __syncthreads();
    for (int i = tid; i < TT * 100; i += blockDim.x) g_dots[i] = 0.f;
    if (tid < NPAIR) {
        int p = tid;
        int b = 1;
        while (tri(b) + b <= p) b++;
        int r = p - tri(b);
        int t = r + 1;                       // source frame, 1..b
        // pose = -(P[b] - P[t-1]) = P[t-1] - P[b]
        float ddx = P[t - 1][0] - P[b][0];
        float ddy = P[t - 1][1] - P[b][1];
        float yaw = P[t - 1][2] - P[b][2];
        g_pose[p * 4 + 0] = cosf(yaw);
        g_pose[p * 4 + 1] = sinf(yaw);
        g_pose[p * 4 + 2] = ddx;
        g_pose[p * 4 + 3] = ddy;
        g_src[p] = t;
    }
}

// ---------------------------------------------------------------------------
// Kernel 2: bilinear warp of the 45 valid (b,t) pairs
// grid: (DD/256, NPAIR), block: 256
// ---------------------------------------------------------------------------
__global__ __launch_bounds__(256) void warp_kernel(const float* __restrict__ ff) {
    int p = blockIdx.y;
    int rem = blockIdx.x * 256 + threadIdx.x;       // element within one image
    int x = rem % WW;
    int yz = rem / WW;
    int y = yz % HH;
    int c = yz / HH;

    float cs = g_pose[p * 4 + 0];
    float sn = g_pose[p * 4 + 1];
    float dx = g_pose[p * 4 + 2];
    float dy = g_pose[p * 4 + 3];
    const float* img = ff + g_src[p] * DD + c * HW;

    float xs = (2.f * (float)x + 1.f) / (float)WW - 1.f;
    float ys = (2.f * (float)y + 1.f) / (float)HH - 1.f;
    float gx = cs * xs + sn * ys + dx;
    float gy = -sn * xs + cs * ys + dy;
    float ix = ((gx + 1.f) * (float)WW - 1.f) * 0.5f;
    float iy = ((gy + 1.f) * (float)HH - 1.f) * 0.5f;

    float ix0 = floorf(ix), iy0 = floorf(iy);
    float ix1 = ix0 + 1.f,  iy1 = iy0 + 1.f;
    float wx1 = ix - ix0, wx0 = 1.f - wx1;
    float wy1 = iy - iy0, wy0 = 1.f - wy1;

    float out = 0.f;
    {
        // 4 corner gathers with zero-padding semantics
        float xf[2] = {ix0, ix1};
        float yf[2] = {iy0, iy1};
        float wx[2] = {wx0, wx1};
        float wy[2] = {wy0, wy1};
        #pragma unroll
        for (int jy = 0; jy < 2; jy++) {
            #pragma unroll
            for (int jx = 0; jx < 2; jx++) {
                bool inb = (xf[jx] >= 0.f) & (xf[jx] < (float)WW) &
                           (yf[jy] >= 0.f) & (yf[jy] < (float)HH);
                int xi = min(max((int)xf[jx], 0), WW - 1);
                int yi = min(max((int)yf[jy], 0), HH - 1);
                float v = img[yi * WW + xi];
                out += (inb ? v : 0.f) * wx[jx] * wy[jy];
            }
        }
    }
    g_warp[p * DD + rem] = out;
}

// ---------------------------------------------------------------------------
// Kernel 3: Gram dots among valid rows of each b.
// grid: (NCHUNK, NDOT), block: 256. blockIdx.y -> (b, i); dots row i vs rows 0..i.
// Row r of batch b: r<b -> g_warp[tri(b)+r], r==b -> ff[b].
// ---------------------------------------------------------------------------
__global__ __launch_bounds__(256) void score_kernel(const float* __restrict__ ff) {
    int pi = blockIdx.y;
    int b = 0;
    while ((b + 1) * (b + 2) / 2 <= pi) b++;
    int i = pi - b * (b + 1) / 2;

    const float4* rows[10];
    #pragma unroll
    for (int j = 0; j < 10; j++) {
        if (j > i) break;
        const float* rp = (j == b) ? (ff + b * DD)
                                   : (g_warp + (tri(b) + j) * DD);
        rows[j] = (const float4*)rp;
    }
    const float4* ri = (i == b) ? (const float4*)(ff + b * DD)
                                : (const float4*)(g_warp + (tri(b) + i) * DD);

    float acc[10];
    #pragma unroll
    for (int j = 0; j < 10; j++) acc[j] = 0.f;

    const int D4 = DD / 4;
    for (int d = blockIdx.x * blockDim.x + threadIdx.x; d < D4;
         d += gridDim.x * blockDim.x) {
        float4 a = ri[d];
        #pragma unroll
        for (int j = 0; j < 10; j++) {
            if (j > i) break;
            float4 v = rows[j][d];
            acc[j] += a.x * v.x + a.y * v.y + a.z * v.z + a.w * v.w;
        }
    }

    // warp-level reduce then atomicAdd from lane 0 of each warp
    #pragma unroll
    for (int j = 0; j < 10; j++) {
        if (j > i) break;
        float v = acc[j];
        #pragma unroll
        for (int o = 16; o > 0; o >>= 1)
            v += __shfl_down_sync(0xffffffffu, v, o);
        if ((threadIdx.x & 31) == 0)
            atomicAdd(&g_dots[b * 100 + i * 10 + j], v);
    }
}

// ---------------------------------------------------------------------------
// Kernel 4: per-b softmax over full 10x10 slot-space scores, mean over t,
// remap weights to row space. One block, thread tid==b handles batch b.
// ---------------------------------------------------------------------------
__global__ void weight_kernel() {
    int b = threadIdx.x;
    if (b >= TT) return;

    float S[10][10];
    for (int t = 0; t < 10; t++) {
        for (int s = 0; s < 10; s++) {
            bool vt = (t >= 9 - b), vs = (s >= 9 - b);
            if (vt && vs) {
                int rt = (t == 9) ? b : (8 - t);
                int rs = (s == 9) ? b : (8 - s);
                int lo = min(rt, rs), hi = max(rt, rs);
                S[t][s] = g_dots[b * 100 + hi * 10 + lo];
            } else {
                S[t][s] = 0.f;
            }
        }
    }
    float wsum[10];
    for (int s = 0; s < 10; s++) wsum[s] = 0.f;
    for (int t = 0; t < 10; t++) {
        float m = S[t][0];
        for (int s = 1; s < 10; s++) m = fmaxf(m, S[t][s]);
        float e[10], z = 0.f;
        for (int s = 0; s < 10; s++) { e[s] = expf(S[t][s] - m); z += e[s]; }
        float inv = 1.f / z;
        for (int s = 0; s < 10; s++) wsum[s] += e[s] * inv;
    }
    // w[slot] = wsum[slot] / T ; remap to row space
    for (int r = 0; r <= b; r++) {
        int slot = (r == b) ? 9 : (8 - r);
        g_wrow[b * 10 + r] = wsum[slot] * (1.f / (float)TT);
    }
}

// ---------------------------------------------------------------------------
// Kernel 5: out[b] = sum_r w[b,r] * row(b,r)
// grid: (DD/256, TT), block 256
// ---------------------------------------------------------------------------
__global__ __launch_bounds__(256) void out_kernel(const float* __restrict__ ff,
                                                  float* __restrict__ out) {
    int b = blockIdx.y;
    __shared__ float w[10];
    if (threadIdx.x < 10) w[threadIdx.x] = g_wrow[b * 10 + threadIdx.x];
    __syncthreads();
    int d = blockIdx.x * 256 + threadIdx.x;
    float acc = w[b] * ff[b * DD + d];
    for (int r = 0; r < b; r++)
        acc += w[r] * g_warp[(tri(b) + r) * DD + d];
    out[b * DD + d] = acc;
}

// ---------------------------------------------------------------------------
extern "C" void kernel_launch(void* const* d_in, const int* in_sizes, int n_in,
                              void* d_out, int out_size) {
    const float* ff = (const float*)d_in[0];   // fuse_feature (T,L,C) = (T,CH,H,W)
    const float* dp = (const float*)d_in[1];   // delta_ego_pos (T,3)
    float* out = (float*)d_out;

    pose_kernel<<<1, 128>>>(dp);
    warp_kernel<<<dim3(DD / 256, NPAIR), 256>>>(ff);
    score_kernel<<<dim3(NCHUNK, NDOT), 256>>>(ff);
    weight_kernel<<<1, 32>>>();
    out_kernel<<<dim3(DD / 256, TT), 256>>>(ff, out);
}

// round 3
// speedup vs baseline: 1.2192x; 1.2192x over previous
#include <cuda_runtime.h>
#include <math.h>

#define TT 10
#define CH 16
#define HH 16
#define WW 264
#define HW (HH*WW)            // 4224
#define DD (CH*HH*WW)         // 67584
#define D4 (DD/4)             // 16896
#define NPAIR 45              // valid (b,t) warp pairs, t in [1,b]
#define NDOT 55               // (b,i) dot-row tasks, i in [0,b]
#define NCHUNK 8

// Scratch (static device globals; no allocation allowed)
__device__ float g_warp[NPAIR * DD];      // 45 warped rows, compact
__device__ float g_dots[TT * 10 * 10];    // per-b row-space Gram (i<=j filled)

__device__ __forceinline__ int tri(int b) { return b * (b - 1) / 2; } // off[b]

// ---------------------------------------------------------------------------
// Kernel 1: bilinear warp of the 45 valid (b,t) pairs. Pose computed inline
// per block; block (0,0) also zeroes g_dots for the score kernel's atomics.
// grid: (D4/256, NPAIR) = (66, 45), block: 256. Each thread does 4 pixels
// (same row/channel, consecutive x) and writes one float4.
// ---------------------------------------------------------------------------
__global__ __launch_bounds__(256) void warp_kernel(const float* __restrict__ ff,
                                                   const float* __restrict__ dp) {
    int p = blockIdx.y;
    int tid = threadIdx.x;

    if (blockIdx.x == 0 && blockIdx.y == 0) {
        for (int i = tid; i < TT * 100; i += 256) g_dots[i] = 0.f;
    }

    __shared__ float sp[4];      // cos, sin, dx, dy
    __shared__ int ssrc;
    if (tid == 0) {
        // derive (b, t) from pair index p: t in [1, b]
        int b = 1;
        while (tri(b) + b <= p) b++;
        int t = p - tri(b) + 1;
        // pose = P[t-1] - P[b], P[k] = cumsum(dp)[:k]
        float ax = 0.f, ay = 0.f, az = 0.f;     // P[t-1]
        float bx = 0.f, by = 0.f, bz = 0.f;     // P[b]
        for (int j = 0; j < b; j++) {
            float d0 = dp[3 * j], d1 = dp[3 * j + 1], d2 = dp[3 * j + 2];
            bx += d0; by += d1; bz += d2;
            if (j < t - 1) { ax += d0; ay += d1; az += d2; }
        }
        float yaw = az - bz;
        sp[0] = cosf(yaw);
        sp[1] = sinf(yaw);
        sp[2] = ax - bx;
        sp[3] = ay - by;
        ssrc = t;
    }
    __syncthreads();

    float cs = sp[0], sn = sp[1], dx = sp[2], dy = sp[3];
    int rem4 = blockIdx.x * 256 + tid;          // float4 index within image
    int pix = rem4 * 4;
    int x0 = pix % WW;                          // WW divisible by 4
    int y  = (pix / WW) % HH;
    int c  = pix / (WW * HH);
    const float* imgc = ff + ssrc * DD + c * HW;

    float ys = (2.f * (float)y + 1.f) / (float)HH - 1.f;
    float o[4];
    #pragma unroll
    for (int k = 0; k < 4; k++) {
        int x = x0 + k;
        float xs = (2.f * (float)x + 1.f) / (float)WW - 1.f;
        float gx = cs * xs + sn * ys + dx;
        float gy = -sn * xs + cs * ys + dy;
        float ix = ((gx + 1.f) * (float)WW - 1.f) * 0.5f;
        float iy = ((gy + 1.f) * (float)HH - 1.f) * 0.5f;

        float ix0 = floorf(ix), iy0 = floorf(iy);
        float wx1 = ix - ix0, wx0 = 1.f - wx1;
        float wy1 = iy - iy0, wy0 = 1.f - wy1;
        float xf[2] = {ix0, ix0 + 1.f};
        float yf[2] = {iy0, iy0 + 1.f};
        float wx[2] = {wx0, wx1};
        float wy[2] = {wy0, wy1};

        float out = 0.f;
        #pragma unroll
        for (int jy = 0; jy < 2; jy++) {
            #pragma unroll
            for (int jx = 0; jx < 2; jx++) {
                bool inb = (xf[jx] >= 0.f) & (xf[jx] < (float)WW) &
                           (yf[jy] >= 0.f) & (yf[jy] < (float)HH);
                int xi = min(max((int)xf[jx], 0), WW - 1);
                int yi = min(max((int)yf[jy], 0), HH - 1);
                float v = imgc[yi * WW + xi];
                out += (inb ? v : 0.f) * wx[jx] * wy[jy];
            }
        }
        o[k] = out;
    }
    ((float4*)g_warp)[p * D4 + rem4] = make_float4(o[0], o[1], o[2], o[3]);
}

// ---------------------------------------------------------------------------
// Kernel 2: Gram dots among valid rows of each b.
// grid: (NCHUNK, NDOT), block: 256. blockIdx.y -> (b, i); dots row i vs rows 0..i.
// Row r of batch b: r<b -> g_warp[tri(b)+r], r==b -> ff[b].
// ---------------------------------------------------------------------------
__global__ __launch_bounds__(256) void score_kernel(const float* __restrict__ ff) {
    int pi = blockIdx.y;
    int b = 0;
    while ((b + 1) * (b + 2) / 2 <= pi) b++;
    int i = pi - b * (b + 1) / 2;

    const float4* rows[10];
    #pragma unroll
    for (int j = 0; j < 10; j++) {
        if (j > i) break;
        const float* rp = (j == b) ? (ff + b * DD)
                                   : (g_warp + (tri(b) + j) * DD);
        rows[j] = (const float4*)rp;
    }
    const float4* ri = (i == b) ? (const float4*)(ff + b * DD)
                                : (const float4*)(g_warp + (tri(b) + i) * DD);

    float acc[10];
    #pragma unroll
    for (int j = 0; j < 10; j++) acc[j] = 0.f;

    for (int d = blockIdx.x * blockDim.x + threadIdx.x; d < D4;
         d += gridDim.x * blockDim.x) {
        float4 a = ri[d];
        #pragma unroll
        for (int j = 0; j < 10; j++) {
            if (j > i) break;
            float4 v = rows[j][d];
            acc[j] += a.x * v.x + a.y * v.y + a.z * v.z + a.w * v.w;
        }
    }

    #pragma unroll
    for (int j = 0; j < 10; j++) {
        if (j > i) break;
        float v = acc[j];
        #pragma unroll
        for (int o = 16; o > 0; o >>= 1)
            v += __shfl_down_sync(0xffffffffu, v, o);
        if ((threadIdx.x & 31) == 0)
            atomicAdd(&g_dots[b * 100 + i * 10 + j], v);
    }
}

// ---------------------------------------------------------------------------
// Kernel 3: fused softmax-weight + weighted row sum.
// grid: (D4/256, TT) = (66, 10), block 256.
// Preamble (threads 0..9): per-b softmax over 10x10 slot-space scores, mean
// over t, remap to row-space weights in shared. Main: float4 weighted sum.
// ---------------------------------------------------------------------------
__global__ __launch_bounds__(256) void out_kernel(const float* __restrict__ ff,
                                                  float* __restrict__ out) {
    int b = blockIdx.y;
    int tid = threadIdx.x;
    __shared__ float contrib[10][10];   // [t][slot] = softmax(S[t])[slot]
    __shared__ float w[10];             // row-space weights

    if (tid < 10) {
        int t = tid;
        float S[10];
        #pragma unroll
        for (int s = 0; s < 10; s++) {
            bool vt = (t >= 9 - b), vs = (s >= 9 - b);
            float v = 0.f;
            if (vt && vs) {
                int rt = (t == 9) ? b : (8 - t);
                int rs = (s == 9) ? b : (8 - s);
                int lo = min(rt, rs), hi = max(rt, rs);
                v = g_dots[b * 100 + hi * 10 + lo];
            }
            S[s] = v;
        }
        float m = S[0];
        #pragma unroll
        for (int s = 1; s < 10; s++) m = fmaxf(m, S[s]);
        float e[10], z = 0.f;
        #pragma unroll
        for (int s = 0; s < 10; s++) { e[s] = expf(S[s] - m); z += e[s]; }
        float inv = 1.f / z;
        #pragma unroll
        for (int s = 0; s < 10; s++) contrib[t][s] = e[s] * inv;
    }
    __syncthreads();
    if (tid < 10) {
        int r = tid;
        float acc = 0.f;
        if (r <= b) {
            int slot = (r == b) ? 9 : (8 - r);
            #pragma unroll
            for (int t = 0; t < 10; t++) acc += contrib[t][slot];
        }
        w[r] = acc * (1.f / (float)TT);
    }
    __syncthreads();

    int d = blockIdx.x * 256 + tid;     // float4 index
    float4 a = ((const float4*)ff)[b * D4 + d];
    float wb = w[b];
    float4 acc = make_float4(wb * a.x, wb * a.y, wb * a.z, wb * a.w);
    for (int r = 0; r < b; r++) {
        float4 v = ((const float4*)g_warp)[(tri(b) + r) * D4 + d];
        float wr = w[r];
        acc.x += wr * v.x;
        acc.y += wr * v.y;
        acc.z += wr * v.z;
        acc.w += wr * v.w;
    }
    ((float4*)out)[b * D4 + d] = acc;
}

// ---------------------------------------------------------------------------
extern "C" void kernel_launch(void* const* d_in, const int* in_sizes, int n_in,
                              void* d_out, int out_size) {
    const float* ff = (const float*)d_in[0];   // fuse_feature (T,L,C) = (T,CH,H,W)
    const float* dp = (const float*)d_in[1];   // delta_ego_pos (T,3)
    float* out = (float*)d_out;

    warp_kernel<<<dim3(D4 / 256, NPAIR), 256>>>(ff, dp);
    score_kernel<<<dim3(NCHUNK, NDOT), 256>>>(ff);
    out_kernel<<<dim3(D4 / 256, TT), 256>>>(ff, out);
}

// round 5
// speedup vs baseline: 1.6655x; 1.3661x over previous
#include <cuda_runtime.h>
#include <math.h>

#define TT 10
#define CH 16
#define HH 16
#define WW 264
#define HW (HH*WW)            // 4224
#define DD (CH*HH*WW)         // 67584
#define D4 (DD/4)             // 16896
#define NPAIR 45              // valid (b,t) warp pairs, t in [1,b]
#define SCHUNK 16             // score kernel chunks per b

// Scratch (static device globals; no allocation allowed)
__device__ float g_warp[NPAIR * DD];      // 45 warped rows, compact
__device__ float g_dots[TT * 10 * 10];    // per-b row-space Gram (i<=j filled)

__device__ __forceinline__ int tri(int b) { return b * (b - 1) / 2; }

// ---------------------------------------------------------------------------
// Kernel 1: bilinear warp of the 45 valid (b,t) pairs.
// grid: (HW/128 = 33, NPAIR), block 128. One thread = one spatial pixel.
// Grid math / corner offsets / weights computed ONCE, reused for 16 channels.
// Block (0,0) zeroes g_dots for the score kernel's atomics.
// ---------------------------------------------------------------------------
__global__ __launch_bounds__(128) void warp_kernel(const float* __restrict__ ff,
                                                   const float* __restrict__ dp) {
    int p = blockIdx.y;
    int tid = threadIdx.x;

    if (blockIdx.x == 0 && p == 0) {
        for (int i = tid; i < TT * 100; i += 128) g_dots[i] = 0.f;
    }

    __shared__ float sp[4];      // cos, sin, dx, dy
    __shared__ int ssrc;
    if (tid == 0) {
        int b = 1;
        while (tri(b) + b <= p) b++;
        int t = p - tri(b) + 1;                 // source frame, 1..b
        float ax = 0.f, ay = 0.f, az = 0.f;     // P[t-1]
        float bx = 0.f, by = 0.f, bz = 0.f;     // P[b]
        for (int j = 0; j < b; j++) {
            float d0 = dp[3 * j], d1 = dp[3 * j + 1], d2 = dp[3 * j + 2];
            bx += d0; by += d1; bz += d2;
            if (j < t - 1) { ax += d0; ay += d1; az += d2; }
        }
        float yaw = az - bz;
        sp[0] = cosf(yaw);
        sp[1] = sinf(yaw);
        sp[2] = ax - bx;
        sp[3] = ay - by;
        ssrc = t;
    }
    __syncthreads();

    float cs = sp[0], sn = sp[1], dx = sp[2], dy = sp[3];
    int pix = blockIdx.x * 128 + tid;           // 0..HW-1
    int x = pix % WW;
    int y = pix / WW;

    float xs = (2.f * (float)x + 1.f) / (float)WW - 1.f;
    float ys = (2.f * (float)y + 1.f) / (float)HH - 1.f;
    float gx = cs * xs + sn * ys + dx;
    float gy = -sn * xs + cs * ys + dy;
    float ix = ((gx + 1.f) * (float)WW - 1.f) * 0.5f;
    float iy = ((gy + 1.f) * (float)HH - 1.f) * 0.5f;

    float ix0f = floorf(ix), iy0f = floorf(iy);
    float wx1 = ix - ix0f, wx0 = 1.f - wx1;
    float wy1 = iy - iy0f, wy0 = 1.f - wy1;

    int ix0 = (int)ix0f, iy0 = (int)iy0f;
    int ix1 = ix0 + 1,   iy1 = iy0 + 1;
    // validity (zeros padding)
    float vx0 = (ix0 >= 0 && ix0 < WW) ? 1.f : 0.f;
    float vx1 = (ix1 >= 0 && ix1 < WW) ? 1.f : 0.f;
    float vy0 = (iy0 >= 0 && iy0 < HH) ? 1.f : 0.f;
    float vy1 = (iy1 >= 0 && iy1 < HH) ? 1.f : 0.f;
    // clamped offsets (safe addresses even when weight is zero)
    int cx0 = min(max(ix0, 0), WW - 1);
    int cx1 = min(max(ix1, 0), WW - 1);
    int cy0 = min(max(iy0, 0), HH - 1);
    int cy1 = min(max(iy1, 0), HH - 1);

    float w00 = wx0 * wy0 * vx0 * vy0;
    float w01 = wx1 * wy0 * vx1 * vy0;
    float w10 = wx0 * wy1 * vx0 * vy1;
    float w11 = wx1 * wy1 * vx1 * vy1;
    int o00 = cy0 * WW + cx0;
    int o01 = cy0 * WW + cx1;
    int o10 = cy1 * WW + cx0;
    int o11 = cy1 * WW + cx1;

    const float* src = ff + ssrc * DD;
    float* dst = g_warp + p * DD + pix;
    #pragma unroll
    for (int c = 0; c < CH; c++) {
        const float* s = src + c * HW;
        float v = w00 * __ldg(s + o00) + w01 * __ldg(s + o01)
                + w10 * __ldg(s + o10) + w11 * __ldg(s + o11);
        dst[c * HW] = v;
    }
}

// ---------------------------------------------------------------------------
// Kernel 2: full per-b Gram. grid: (SCHUNK, TT), block 256.
// Each block loads a chunk of all (b+1) rows and accumulates ALL
// (b+1)(b+2)/2 pairwise dots in registers; each row is read once per b.
// ---------------------------------------------------------------------------
__global__ __launch_bounds__(256) void score_kernel(const float* __restrict__ ff) {
    int b = blockIdx.y;
    int nr = b + 1;

    const float4* rows[10];
    #pragma unroll
    for (int j = 0; j < 10; j++) {
        if (j < nr) {
            const float* rp = (j == b) ? (ff + b * DD)
                                       : (g_warp + (tri(b) + j) * DD);
            rows[j] = (const float4*)rp;
        }
    }

    float acc[55];
    #pragma unroll
    for (int k = 0; k < 55; k++) acc[k] = 0.f;

    for (int d = blockIdx.x * 256 + threadIdx.x; d < D4; d += SCHUNK * 256) {
        float4 v[10];
        #pragma unroll
        for (int j = 0; j < 10; j++)
            if (j < nr) v[j] = rows[j][d];
        #pragma unroll
        for (int i = 0; i < 10; i++) {
            if (i < nr) {
                #pragma unroll
                for (int j = 0; j <= i; j++) {
                    acc[i * (i + 1) / 2 + j] +=
                        v[i].x * v[j].x + v[i].y * v[j].y +
                        v[i].z * v[j].z + v[i].w * v[j].w;
                }
            }
        }
    }

    // warp-level reduce each dot, lane 0 atomics into g_dots
    #pragma unroll
    for (int i = 0; i < 10; i++) {
        if (i < nr) {
            #pragma unroll
            for (int j = 0; j <= i; j++) {
                float v = acc[i * (i + 1) / 2 + j];
                #pragma unroll
                for (int o = 16; o > 0; o >>= 1)
                    v += __shfl_down_sync(0xffffffffu, v, o);
                if ((threadIdx.x & 31) == 0)
                    atomicAdd(&g_dots[b * 100 + i * 10 + j], v);
            }
        }
    }
}

// ---------------------------------------------------------------------------
// Kernel 3: fused softmax-weight + weighted row sum.
// grid: (D4/256, TT) = (66, 10), block 256.
// ---------------------------------------------------------------------------
__global__ __launch_bounds__(256) void out_kernel(const float* __restrict__ ff,
                                                  float* __restrict__ out) {
    int b = blockIdx.y;
    int tid = threadIdx.x;
    __shared__ float contrib[10][10];   // [t][slot] = softmax(S[t])[slot]
    __shared__ float w[10];             // row-space weights

    if (tid < 10) {
        int t = tid;
        float S[10];
        #pragma unroll
        for (int s = 0; s < 10; s++) {
            bool vt = (t >= 9 - b), vs = (s >= 9 - b);
            float v = 0.f;
            if (vt && vs) {
                int rt = (t == 9) ? b : (8 - t);
                int rs = (s == 9) ? b : (8 - s);
                int lo = min(rt, rs), hi = max(rt, rs);
                v = g_dots[b * 100 + hi * 10 + lo];
            }
            S[s] = v;
        }
        float m = S[0];
        #pragma unroll
        for (int s = 1; s < 10; s++) m = fmaxf(m, S[s]);
        float e[10], z = 0.f;
        #pragma unroll
        for (int s = 0; s < 10; s++) { e[s] = expf(S[s] - m); z += e[s]; }
        float inv = 1.f / z;
        #pragma unroll
        for (int s = 0; s < 10; s++) contrib[t][s] = e[s] * inv;
    }
    __syncthreads();
    if (tid < 10) {
        int r = tid;
        float acc = 0.f;
        if (r <= b) {
            int slot = (r == b) ? 9 : (8 - r);
            #pragma unroll
            for (int t = 0; t < 10; t++) acc += contrib[t][slot];
        }
        w[r] = acc * (1.f / (float)TT);
    }
    __syncthreads();

    int d = blockIdx.x * 256 + tid;     // float4 index
    float4 a = ((const float4*)ff)[b * D4 + d];
    float wb = w[b];
    float4 acc = make_float4(wb * a.x, wb * a.y, wb * a.z, wb * a.w);
    for (int r = 0; r < b; r++) {
        float4 v = ((const float4*)g_warp)[(tri(b) + r) * D4 + d];
        float wr = w[r];
        acc.x += wr * v.x;
        acc.y += wr * v.y;
        acc.z += wr * v.z;
        acc.w += wr * v.w;
    }
    ((float4*)out)[b * D4 + d] = acc;
}

// ---------------------------------------------------------------------------
extern "C" void kernel_launch(void* const* d_in, const int* in_sizes, int n_in,
                              void* d_out, int out_size) {
    const float* ff = (const float*)d_in[0];   // fuse_feature (T,L,C) = (T,CH,H,W)
    const float* dp = (const float*)d_in[1];   // delta_ego_pos (T,3)
    float* out = (float*)d_out;

    warp_kernel<<<dim3(HW / 128, NPAIR), 128>>>(ff, dp);
    score_kernel<<<dim3(SCHUNK, TT), 256>>>(ff);
    out_kernel<<<dim3(D4 / 256, TT), 256>>>(ff, out);
}